// round 1
// baseline (speedup 1.0000x reference)
#include <cuda_runtime.h>
#include <math.h>

#define BDIM 256
#define IDIM 256
#define HDIM 512
#define SDIM 64
#define GE 2048   // 4*H
#define GD 1024   // 4*I

// ---------------- scratch (device globals: allocation-free contract) ----------
__device__ float g_xT[SDIM * BDIM * IDIM];            // 16.8 MB  x transposed (S,B,I)
__device__ float g_Gx[(size_t)SDIM * BDIM * GE];      // 134 MB   x@Wih^T + biases, all steps
__device__ float g_part[4 * BDIM * GE];               // 8.4 MB   split-K partials
__device__ float g_h[BDIM * HDIM];                    // hidden state
__device__ float g_enc[SDIM * BDIM * HDIM];           // 33.5 MB  elu(enc) (then residual-chained)
__device__ float g_hd[SDIM * BDIM * IDIM];            // 16.8 MB  decoder hd

__device__ __forceinline__ float sigf(float x) { return 1.0f / (1.0f + expf(-x)); }

// ---------------- x (B,I,S) -> xT (S,B,I) ------------------------------------
__global__ __launch_bounds__(256) void k_transpose_x(const float* __restrict__ x) {
    __shared__ float tile[32][65];
    int b  = blockIdx.x >> 3;
    int i0 = (blockIdx.x & 7) * 32;
    int tid = threadIdx.x;
    int s = tid & 63, it = tid >> 6;
#pragma unroll
    for (int j = 0; j < 8; j++) {
        int i = it * 8 + j;
        tile[i][s] = x[(b * IDIM + i0 + i) * SDIM + s];
    }
    __syncthreads();
    int i2 = tid & 31, sq = tid >> 5;
#pragma unroll
    for (int j = 0; j < 8; j++) {
        int ss = sq * 8 + j;
        g_xT[(ss * BDIM + b) * IDIM + i0 + i2] = tile[i2][ss];
    }
}

__global__ void k_zero_h() {
    int i = blockIdx.x * 256 + threadIdx.x;
    g_h[i] = 0.0f;
}

// ---------------- Gx[s] = xT[s] @ Wih_enc[s]^T + bih + bhh  (batched NT GEMM) -
// per s: M=256, N=2048, K=256.  Tile 64x128, BK=16, 256 thr, 4x8 micro.
__global__ __launch_bounds__(256) void k_gemm_gx(const float* __restrict__ Wih,
                                                 const float* __restrict__ bih,
                                                 const float* __restrict__ bhh) {
    int s  = blockIdx.y;
    int bm = blockIdx.x & 3;
    int bn = blockIdx.x >> 2;
    const float* A = g_xT + (s * BDIM + bm * 64) * IDIM;
    const float* W = Wih + ((size_t)s * GE + bn * 128) * IDIM;
    __shared__ float As[16][68];
    __shared__ float Ws[16][132];
    int tid = threadIdx.x;
    int tm = tid >> 4, tn = tid & 15;
    float acc[4][8] = {};
    int la_r = tid >> 2, la_k = (tid & 3) << 2;

    for (int k0 = 0; k0 < IDIM; k0 += 16) {
        float4 a = *(const float4*)(A + la_r * IDIM + k0 + la_k);
        As[la_k + 0][la_r] = a.x; As[la_k + 1][la_r] = a.y;
        As[la_k + 2][la_r] = a.z; As[la_k + 3][la_r] = a.w;
#pragma unroll
        for (int r = 0; r < 2; r++) {
            int idx = tid + 256 * r;
            int rw = idx >> 2, kk = (idx & 3) << 2;
            float4 w = *(const float4*)(W + rw * IDIM + k0 + kk);
            Ws[kk + 0][rw] = w.x; Ws[kk + 1][rw] = w.y;
            Ws[kk + 2][rw] = w.z; Ws[kk + 3][rw] = w.w;
        }
        __syncthreads();
#pragma unroll
        for (int k = 0; k < 16; k++) {
            float4 av = *(const float4*)&As[k][tm << 2];
            float4 b0 = *(const float4*)&Ws[k][tn << 3];
            float4 b1 = *(const float4*)&Ws[k][(tn << 3) + 4];
            float am[4] = {av.x, av.y, av.z, av.w};
            float bv[8] = {b0.x, b0.y, b0.z, b0.w, b1.x, b1.y, b1.z, b1.w};
#pragma unroll
            for (int i = 0; i < 4; i++)
#pragma unroll
                for (int j = 0; j < 8; j++)
                    acc[i][j] = fmaf(am[i], bv[j], acc[i][j]);
        }
        __syncthreads();
    }
    const float* bi = bih + s * GE + bn * 128;
    const float* bh = bhh + s * GE + bn * 128;
    float* C = g_Gx + ((size_t)(s * BDIM) + bm * 64) * GE + bn * 128;
#pragma unroll
    for (int i = 0; i < 4; i++) {
        int row = (tm << 2) + i;
#pragma unroll
        for (int j = 0; j < 8; j++) {
            int col = (tn << 3) + j;
            C[(size_t)row * GE + col] = acc[i][j] + bi[col] + bh[col];
        }
    }
}

// ---------------- encoder step: split-K GEMM  h @ Whh_enc[s]^T ----------------
// grid 128 = bm(4) * nh(8) * kc(4). Block computes 64 rows x (4 gates x 64 h-cols)
// for one K-chunk of 128; writes partials.
__global__ __launch_bounds__(256) void k_enc_gemm(const float* __restrict__ Whh, int s) {
    int bx = blockIdx.x;
    int bm = bx & 3, nh = (bx >> 2) & 7, kc = bx >> 5;
    const float* A = g_h + bm * 64 * HDIM + kc * 128;
    const float* W = Whh + (size_t)s * GE * HDIM + kc * 128;
    __shared__ float As[16][68];
    __shared__ float Ws[16][260];
    int tid = threadIdx.x;
    int tm = tid >> 5, tn = tid & 31;
    float acc[8][4][2] = {};
    int la_r = tid >> 2, la_k = (tid & 3) << 2;

    for (int k0 = 0; k0 < 128; k0 += 16) {
        float4 a = *(const float4*)(A + la_r * HDIM + k0 + la_k);
        As[la_k + 0][la_r] = a.x; As[la_k + 1][la_r] = a.y;
        As[la_k + 2][la_r] = a.z; As[la_k + 3][la_r] = a.w;
#pragma unroll
        for (int r = 0; r < 4; r++) {
            int idx = tid + 256 * r;
            int grow = idx >> 2, kk = (idx & 3) << 2;
            int wr = ((grow >> 6) << 9) + nh * 64 + (grow & 63);  // grp*512 + hrow
            float4 w = *(const float4*)(W + (size_t)wr * HDIM + k0 + kk);
            Ws[kk + 0][grow] = w.x; Ws[kk + 1][grow] = w.y;
            Ws[kk + 2][grow] = w.z; Ws[kk + 3][grow] = w.w;
        }
        __syncthreads();
#pragma unroll
        for (int k = 0; k < 16; k++) {
            float4 a0 = *(const float4*)&As[k][tm << 3];
            float4 a1 = *(const float4*)&As[k][(tm << 3) + 4];
            float am[8] = {a0.x, a0.y, a0.z, a0.w, a1.x, a1.y, a1.z, a1.w};
#pragma unroll
            for (int g = 0; g < 4; g++) {
                float2 w = *(const float2*)&Ws[k][(g << 6) + (tn << 1)];
#pragma unroll
                for (int i = 0; i < 8; i++) {
                    acc[i][g][0] = fmaf(am[i], w.x, acc[i][g][0]);
                    acc[i][g][1] = fmaf(am[i], w.y, acc[i][g][1]);
                }
            }
        }
        __syncthreads();
    }
    float* P = g_part + kc * BDIM * GE;
#pragma unroll
    for (int i = 0; i < 8; i++) {
        int row = bm * 64 + (tm << 3) + i;
#pragma unroll
        for (int g = 0; g < 4; g++) {
            int col = (g << 9) + nh * 64 + (tn << 1);
            *(float2*)&P[row * GE + col] = make_float2(acc[i][g][0], acc[i][g][1]);
        }
    }
}

// ---------------- encoder step combine: reduce partials + LSTM pointwise ------
__global__ __launch_bounds__(256) void k_enc_combine(int s) {
    int idx = blockIdx.x * 256 + threadIdx.x;  // 0..131071 over (b,h)
    int b = idx >> 9, h = idx & 511;
    const float* G = g_Gx + ((size_t)s * BDIM + b) * GE;
    float gv[4];
#pragma unroll
    for (int g = 0; g < 4; g++) {
        int col = (g << 9) + h;
        float v = G[col];
        v += g_part[0 * BDIM * GE + b * GE + col];
        v += g_part[1 * BDIM * GE + b * GE + col];
        v += g_part[2 * BDIM * GE + b * GE + col];
        v += g_part[3 * BDIM * GE + b * GE + col];
        gv[g] = v;
    }
    float hp = g_h[idx];
    float c  = sigf(gv[1]) * hp + sigf(gv[0]) * tanhf(gv[2]);
    float hn = sigf(gv[3]) * tanhf(c);
    g_h[idx] = hn;
    g_enc[s * BDIM * HDIM + idx] = hn > 0.0f ? hn : expm1f(hn);  // elu fused
}

// ---------------- strided residual chain (per-element independent) ------------
__global__ void k_chain() {
    int e = blockIdx.x * 256 + threadIdx.x;  // 131072 elements
    float prev = g_enc[60 * BDIM * HDIM + e];  // original enc[60] (row untouched yet)
#pragma unroll
    for (int k = 0; k < 16; k++) {
        int off = (k * 4) * BDIM * HDIM + e;
        float v = 0.5f * g_enc[off] + 0.5f * prev;
        g_enc[off] = v;
        prev = v;
    }
}

// ---------------- decoder: gates (i,g,o only; f unused) + pointwise -----------
// per sd: A = enc[63-sd] (256x512), W = Wih_dec[sd]; N = 3 groups x 64 i-cols/block
__global__ __launch_bounds__(256) void k_dec(const float* __restrict__ Wd,
                                             const float* __restrict__ bid,
                                             const float* __restrict__ bhd) {
    int sd = blockIdx.y;
    int bm = blockIdx.x & 3;
    int bi = blockIdx.x >> 2;
    const float* A = g_enc + ((63 - sd) * BDIM + bm * 64) * HDIM;
    const float* W = Wd + (size_t)sd * GD * HDIM;
    __shared__ float As[16][68];
    __shared__ float Ws[16][196];
    int tid = threadIdx.x;
    int tm = tid >> 5, tn = tid & 31;
    float acc[8][3][2] = {};
    int la_r = tid >> 2, la_k = (tid & 3) << 2;

    for (int k0 = 0; k0 < HDIM; k0 += 16) {
        float4 a = *(const float4*)(A + la_r * HDIM + k0 + la_k);
        As[la_k + 0][la_r] = a.x; As[la_k + 1][la_r] = a.y;
        As[la_k + 2][la_r] = a.z; As[la_k + 3][la_r] = a.w;
#pragma unroll
        for (int r = 0; r < 3; r++) {
            int idx = tid + 256 * r;
            int grow = idx >> 2, kk = (idx & 3) << 2;
            int grp = grow >> 6;                       // 0,1,2
            int gg = (grp == 0) ? 0 : ((grp == 1) ? 2 : 3);  // i,g,o groups
            int wr = gg * IDIM + bi * 64 + (grow & 63);
            float4 w = *(const float4*)(W + (size_t)wr * HDIM + k0 + kk);
            Ws[kk + 0][grow] = w.x; Ws[kk + 1][grow] = w.y;
            Ws[kk + 2][grow] = w.z; Ws[kk + 3][grow] = w.w;
        }
        __syncthreads();
#pragma unroll
        for (int k = 0; k < 16; k++) {
            float4 a0 = *(const float4*)&As[k][tm << 3];
            float4 a1 = *(const float4*)&As[k][(tm << 3) + 4];
            float am[8] = {a0.x, a0.y, a0.z, a0.w, a1.x, a1.y, a1.z, a1.w};
#pragma unroll
            for (int g = 0; g < 3; g++) {
                float2 w = *(const float2*)&Ws[k][(g << 6) + (tn << 1)];
#pragma unroll
                for (int i = 0; i < 8; i++) {
                    acc[i][g][0] = fmaf(am[i], w.x, acc[i][g][0]);
                    acc[i][g][1] = fmaf(am[i], w.y, acc[i][g][1]);
                }
            }
        }
        __syncthreads();
    }
    int colb = bi * 64 + (tn << 1);
    const float* B1 = bid + sd * GD;
    const float* B2 = bhd + sd * GD;
    float bias_i[2], bias_g[2], bias_o[2];
#pragma unroll
    for (int c = 0; c < 2; c++) {
        bias_i[c] = B1[0 * IDIM + colb + c] + B2[0 * IDIM + colb + c];
        bias_g[c] = B1[2 * IDIM + colb + c] + B2[2 * IDIM + colb + c];
        bias_o[c] = B1[3 * IDIM + colb + c] + B2[3 * IDIM + colb + c];
    }
#pragma unroll
    for (int i = 0; i < 8; i++) {
        int row = bm * 64 + (tm << 3) + i;
        float2 outv;
        float ov0, ov1;
        {
            float iv = acc[i][0][0] + bias_i[0];
            float gl = acc[i][1][0] + bias_g[0];
            float ov = acc[i][2][0] + bias_o[0];
            float cc = sigf(iv) * tanhf(gl);
            ov0 = sigf(ov) * tanhf(cc);
        }
        {
            float iv = acc[i][0][1] + bias_i[1];
            float gl = acc[i][1][1] + bias_g[1];
            float ov = acc[i][2][1] + bias_o[1];
            float cc = sigf(iv) * tanhf(gl);
            ov1 = sigf(ov) * tanhf(cc);
        }
        outv.x = ov0; outv.y = ov1;
        *(float2*)&g_hd[((sd * BDIM) + row) * IDIM + colb] = outv;
    }
}

// ---------------- cumsum(4) + tanh + reverse + transpose to (B,I,S) -----------
__global__ void k_final(float* __restrict__ out) {
    int idx = blockIdx.x * 256 + threadIdx.x;  // 1,048,576 = B*I*(S/4)
    int i = idx & 255;
    int q = (idx >> 8) & 15;
    int b = idx >> 12;
    int base = (4 * q * BDIM + b) * IDIM + i;
    float a0 = g_hd[base];
    float a1 = g_hd[base + 1 * BDIM * IDIM];
    float a2 = g_hd[base + 2 * BDIM * IDIM];
    float a3 = g_hd[base + 3 * BDIM * IDIM];
    float r0 = a0, r1 = r0 + a1, r2 = r1 + a2, r3 = r2 + a3;
    // out[b][i][63-4q-r] = tanh(run_r)  ->  contiguous float4 at s = 60-4q
    float4 v = make_float4(tanhf(r3), tanhf(r2), tanhf(r1), tanhf(r0));
    *(float4*)(out + (size_t)(b * IDIM + i) * SDIM + (60 - 4 * q)) = v;
}

// ---------------- launch ------------------------------------------------------
extern "C" void kernel_launch(void* const* d_in, const int* in_sizes, int n_in,
                              void* d_out, int out_size) {
    const float* x       = (const float*)d_in[0];
    const float* Wih_enc = (const float*)d_in[1];
    const float* Whh_enc = (const float*)d_in[2];
    const float* bih_enc = (const float*)d_in[3];
    const float* bhh_enc = (const float*)d_in[4];
    const float* Wih_dec = (const float*)d_in[5];
    // d_in[6] = Whh_dec: unused by the reference computation
    const float* bih_dec = (const float*)d_in[7];
    const float* bhh_dec = (const float*)d_in[8];
    float* out = (float*)d_out;

    k_transpose_x<<<2048, 256>>>(x);
    k_zero_h<<<512, 256>>>();
    k_gemm_gx<<<dim3(64, 64), 256>>>(Wih_enc, bih_enc, bhh_enc);
    for (int s = 0; s < SDIM; s++) {
        k_enc_gemm<<<128, 256>>>(Whh_enc, s);
        k_enc_combine<<<512, 256>>>(s);
    }
    k_chain<<<512, 256>>>();
    k_dec<<<dim3(16, 64), 256>>>(Wih_dec, bih_dec, bhh_dec);
    k_final<<<4096, 256>>>(out);
}

// round 2
// speedup vs baseline: 1.3484x; 1.3484x over previous
#include <cuda_runtime.h>
#include <math.h>
#include <stdint.h>

#define BDIM 256
#define IDIM 256
#define HDIM 512
#define SDIM 64
#define GE 2048   // 4*H
#define GD 1024   // 4*I

// ---------------- scratch (device globals: allocation-free contract) ----------
__device__ float g_xT[SDIM * BDIM * IDIM];            // x transposed (S,B,I)
__device__ float g_Gx[(size_t)SDIM * BDIM * GE];      // x@Wih^T + biases, all steps
__device__ float g_hA[BDIM * HDIM];                   // hidden state ping
__device__ float g_hB[BDIM * HDIM];                   // hidden state pong
__device__ float g_enc[SDIM * BDIM * HDIM];           // elu(enc) (then residual-chained)
__device__ float g_hd[SDIM * BDIM * IDIM];            // decoder hd

__device__ __forceinline__ float sigf(float x) { return 1.0f / (1.0f + expf(-x)); }

__device__ __forceinline__ float to_tf32(float x) {
    uint32_t u;
    asm("cvt.rna.tf32.f32 %0, %1;" : "=r"(u) : "f"(x));
    return __uint_as_float(u);
}

__device__ __forceinline__ void mma8(float c[4], uint32_t a0, uint32_t a1,
                                     uint32_t a2, uint32_t a3,
                                     uint32_t b0, uint32_t b1) {
    asm volatile(
        "mma.sync.aligned.m16n8k8.row.col.f32.tf32.tf32.f32 "
        "{%0,%1,%2,%3}, {%4,%5,%6,%7}, {%8,%9}, {%0,%1,%2,%3};\n"
        : "+f"(c[0]), "+f"(c[1]), "+f"(c[2]), "+f"(c[3])
        : "r"(a0), "r"(a1), "r"(a2), "r"(a3), "r"(b0), "r"(b1));
}

__device__ __forceinline__ uint32_t fbits(float x) { return __float_as_uint(x); }

// ---------------- x (B,I,S) -> xT (S,B,I) ------------------------------------
__global__ __launch_bounds__(256) void k_transpose_x(const float* __restrict__ x) {
    __shared__ float tile[32][65];
    int b  = blockIdx.x >> 3;
    int i0 = (blockIdx.x & 7) * 32;
    int tid = threadIdx.x;
    int s = tid & 63, it = tid >> 6;
#pragma unroll
    for (int j = 0; j < 8; j++) {
        int i = it * 8 + j;
        tile[i][s] = x[(b * IDIM + i0 + i) * SDIM + s];
    }
    __syncthreads();
    int i2 = tid & 31, sq = tid >> 5;
#pragma unroll
    for (int j = 0; j < 8; j++) {
        int ss = sq * 8 + j;
        g_xT[(ss * BDIM + b) * IDIM + i0 + i2] = tile[i2][ss];
    }
}

__global__ void k_zero_h() {
    int i = blockIdx.x * 256 + threadIdx.x;
    g_hA[i] = 0.0f;
}

// ---------------- Gx[s] = xT[s] @ Wih_enc[s]^T + bih + bhh (tf32 mma) ---------
// grid (128, 64): bm=8 tiles of 32 rows, bn=16 tiles of 128 cols. K=256.
__global__ __launch_bounds__(256) void k_gx(const float* __restrict__ Wih,
                                            const float* __restrict__ bih,
                                            const float* __restrict__ bhh) {
    __shared__ float As[32][36];
    __shared__ float Ws[128][36];
    int tid = threadIdx.x;
    int s = blockIdx.y;
    int bm = blockIdx.x & 7;
    int bn = blockIdx.x >> 3;

    int lr = tid >> 3;        // 0..31
    int lk = (tid & 7) * 4;   // 0..28

    const float* Ag = g_xT + (size_t)(s * BDIM + bm * 32 + lr) * IDIM + lk;
    const float* Bg[4];
#pragma unroll
    for (int r = 0; r < 4; r++)
        Bg[r] = Wih + ((size_t)s * GE + bn * 128 + r * 32 + lr) * IDIM + lk;

    int warp = tid >> 5, lane = tid & 31;
    int wm = warp >> 2, wn = warp & 3;
    int g = lane >> 2, t = lane & 3;
    int m0 = wm * 16, n0 = wn * 32;

    float c[4][4] = {};
    float4 pa = *(const float4*)Ag;
    float4 pb[4];
#pragma unroll
    for (int r = 0; r < 4; r++) pb[r] = *(const float4*)Bg[r];

    for (int it = 0; it < 8; it++) {
        As[lr][lk + 0] = to_tf32(pa.x); As[lr][lk + 1] = to_tf32(pa.y);
        As[lr][lk + 2] = to_tf32(pa.z); As[lr][lk + 3] = to_tf32(pa.w);
#pragma unroll
        for (int r = 0; r < 4; r++) {
            int jr = r * 32 + lr;
            Ws[jr][lk + 0] = to_tf32(pb[r].x); Ws[jr][lk + 1] = to_tf32(pb[r].y);
            Ws[jr][lk + 2] = to_tf32(pb[r].z); Ws[jr][lk + 3] = to_tf32(pb[r].w);
        }
        __syncthreads();
        if (it < 7) {
            Ag += 32;
            pa = *(const float4*)Ag;
#pragma unroll
            for (int r = 0; r < 4; r++) { Bg[r] += 32; pb[r] = *(const float4*)Bg[r]; }
        }
#pragma unroll
        for (int kk = 0; kk < 32; kk += 8) {
            uint32_t a0 = fbits(As[m0 + g][kk + t]);
            uint32_t a1 = fbits(As[m0 + g + 8][kk + t]);
            uint32_t a2 = fbits(As[m0 + g][kk + t + 4]);
            uint32_t a3 = fbits(As[m0 + g + 8][kk + t + 4]);
#pragma unroll
            for (int f = 0; f < 4; f++) {
                uint32_t b0 = fbits(Ws[n0 + f * 8 + g][kk + t]);
                uint32_t b1 = fbits(Ws[n0 + f * 8 + g][kk + t + 4]);
                mma8(c[f], a0, a1, a2, a3, b0, b1);
            }
        }
        __syncthreads();
    }
    // epilogue: add biases, store
#pragma unroll
    for (int f = 0; f < 4; f++) {
        int col = bn * 128 + n0 + f * 8 + 2 * t;
        float bi0 = bih[s * GE + col] + bhh[s * GE + col];
        float bi1 = bih[s * GE + col + 1] + bhh[s * GE + col + 1];
        size_t r0 = ((size_t)s * BDIM + bm * 32 + m0 + g) * GE + col;
        size_t r1 = ((size_t)s * BDIM + bm * 32 + m0 + g + 8) * GE + col;
        *(float2*)&g_Gx[r0] = make_float2(c[f][0] + bi0, c[f][1] + bi1);
        *(float2*)&g_Gx[r1] = make_float2(c[f][2] + bi0, c[f][3] + bi1);
    }
}

// ---------------- encoder step: h@Whh^T (tf32 mma) + fused LSTM pointwise -----
// grid 128 = bm(8 tiles of 32 rows) x bh(16 tiles of 32 h-cols).
// CTA output: 32 rows x (4 gates x 32 h-cols). K = 512, no split-K.
__global__ __launch_bounds__(256) void k_enc_step(const float* __restrict__ Whh, int s) {
    __shared__ float As[32][36];
    __shared__ float Ws[128][36];
    __shared__ float Cs[32][132];
    int tid = threadIdx.x;
    int bm = blockIdx.x & 7;
    int bh = blockIdx.x >> 3;

    const float* hin = (s & 1) ? g_hB : g_hA;
    float* hout      = (s & 1) ? g_hA : g_hB;
    const float* W0 = Whh + (size_t)s * GE * HDIM;

    int lr = tid >> 3;
    int lk = (tid & 7) * 4;

    const float* Ag = hin + (size_t)(bm * 32 + lr) * HDIM + lk;
    const float* Bg[4];
#pragma unroll
    for (int r = 0; r < 4; r++)
        Bg[r] = W0 + (size_t)(r * HDIM + bh * 32 + lr) * HDIM + lk;

    int warp = tid >> 5, lane = tid & 31;
    int wm = warp >> 2, wn = warp & 3;
    int g = lane >> 2, t = lane & 3;
    int m0 = wm * 16, n0 = wn * 32;

    float c[4][4] = {};
    float4 pa = *(const float4*)Ag;
    float4 pb[4];
#pragma unroll
    for (int r = 0; r < 4; r++) pb[r] = *(const float4*)Bg[r];

    for (int it = 0; it < 16; it++) {
        As[lr][lk + 0] = to_tf32(pa.x); As[lr][lk + 1] = to_tf32(pa.y);
        As[lr][lk + 2] = to_tf32(pa.z); As[lr][lk + 3] = to_tf32(pa.w);
#pragma unroll
        for (int r = 0; r < 4; r++) {
            int jr = r * 32 + lr;
            Ws[jr][lk + 0] = to_tf32(pb[r].x); Ws[jr][lk + 1] = to_tf32(pb[r].y);
            Ws[jr][lk + 2] = to_tf32(pb[r].z); Ws[jr][lk + 3] = to_tf32(pb[r].w);
        }
        __syncthreads();
        if (it < 15) {
            Ag += 32;
            pa = *(const float4*)Ag;
#pragma unroll
            for (int r = 0; r < 4; r++) { Bg[r] += 32; pb[r] = *(const float4*)Bg[r]; }
        }
#pragma unroll
        for (int kk = 0; kk < 32; kk += 8) {
            uint32_t a0 = fbits(As[m0 + g][kk + t]);
            uint32_t a1 = fbits(As[m0 + g + 8][kk + t]);
            uint32_t a2 = fbits(As[m0 + g][kk + t + 4]);
            uint32_t a3 = fbits(As[m0 + g + 8][kk + t + 4]);
#pragma unroll
            for (int f = 0; f < 4; f++) {
                uint32_t b0 = fbits(Ws[n0 + f * 8 + g][kk + t]);
                uint32_t b1 = fbits(Ws[n0 + f * 8 + g][kk + t + 4]);
                mma8(c[f], a0, a1, a2, a3, b0, b1);
            }
        }
        __syncthreads();
    }
    // dump accumulators to smem for cross-thread gate gather
#pragma unroll
    for (int f = 0; f < 4; f++) {
        int col0 = n0 + f * 8 + 2 * t;
        *(float2*)&Cs[m0 + g][col0]     = make_float2(c[f][0], c[f][1]);
        *(float2*)&Cs[m0 + g + 8][col0] = make_float2(c[f][2], c[f][3]);
    }
    __syncthreads();
    // fused LSTM pointwise + elu
    int row = tid >> 3;
    int hcb = (tid & 7) * 4;
    int brow = bm * 32 + row;
    const float* Gxp = g_Gx + ((size_t)s * BDIM + brow) * GE + bh * 32;
    float4 hv, ev;
#pragma unroll
    for (int q = 0; q < 4; q++) {
        int hc = hcb + q;
        float gi = Cs[row][0 * 32 + hc] + Gxp[0 * HDIM + hc];
        float gf = Cs[row][1 * 32 + hc] + Gxp[1 * HDIM + hc];
        float gg = Cs[row][2 * 32 + hc] + Gxp[2 * HDIM + hc];
        float go = Cs[row][3 * 32 + hc] + Gxp[3 * HDIM + hc];
        float hp = hin[(size_t)brow * HDIM + bh * 32 + hc];
        float cc = sigf(gf) * hp + sigf(gi) * tanhf(gg);
        float hn = sigf(go) * tanhf(cc);
        (&hv.x)[q] = hn;
        (&ev.x)[q] = hn > 0.0f ? hn : expm1f(hn);
    }
    *(float4*)&hout[(size_t)brow * HDIM + bh * 32 + hcb] = hv;
    *(float4*)&g_enc[(size_t)s * BDIM * HDIM + brow * HDIM + bh * 32 + hcb] = ev;
}

// ---------------- strided residual chain (per-element independent) ------------
__global__ void k_chain() {
    int e = blockIdx.x * 256 + threadIdx.x;
    float prev = g_enc[60 * BDIM * HDIM + e];
#pragma unroll
    for (int k = 0; k < 16; k++) {
        int off = (k * 4) * BDIM * HDIM + e;
        float v = 0.5f * g_enc[off] + 0.5f * prev;
        g_enc[off] = v;
        prev = v;
    }
}

// ---------------- decoder: enc_rev @ Wih_dec^T (i,g,o gates only) + pointwise -
// grid (64, 64): bm=8 tiles of 32 rows, bi=8 tiles of 32 i-cols; y = sd.
// CTA output: 32 rows x (3 gates x 32 i-cols) = 32 x 96. K = 512.
__global__ __launch_bounds__(256) void k_dec(const float* __restrict__ Wd,
                                             const float* __restrict__ bid,
                                             const float* __restrict__ bhd) {
    __shared__ float As[32][36];
    __shared__ float Ws[96][36];
    __shared__ float Cs[32][100];
    int tid = threadIdx.x;
    int sd = blockIdx.y;
    int bm = blockIdx.x & 7;
    int bi = blockIdx.x >> 3;

    int lr = tid >> 3;
    int lk = (tid & 7) * 4;

    const float* Ag = g_enc + ((size_t)(63 - sd) * BDIM + bm * 32 + lr) * HDIM + lk;
    const int agate[3] = {0, 2, 3};  // i, g, o rows of Wd (f unused)
    const float* Bg[3];
#pragma unroll
    for (int r = 0; r < 3; r++)
        Bg[r] = Wd + ((size_t)sd * GD + agate[r] * IDIM + bi * 32 + lr) * HDIM + lk;

    int warp = tid >> 5, lane = tid & 31;
    int wm = warp >> 2, wn = warp & 3;
    int g = lane >> 2, t = lane & 3;
    int m0 = wm * 16, n0 = wn * 24;  // 4 warps x 24 = 96 n-cols

    float c[3][4] = {};
    float4 pa = *(const float4*)Ag;
    float4 pb[3];
#pragma unroll
    for (int r = 0; r < 3; r++) pb[r] = *(const float4*)Bg[r];

    for (int it = 0; it < 16; it++) {
        As[lr][lk + 0] = to_tf32(pa.x); As[lr][lk + 1] = to_tf32(pa.y);
        As[lr][lk + 2] = to_tf32(pa.z); As[lr][lk + 3] = to_tf32(pa.w);
#pragma unroll
        for (int r = 0; r < 3; r++) {
            int jr = r * 32 + lr;
            Ws[jr][lk + 0] = to_tf32(pb[r].x); Ws[jr][lk + 1] = to_tf32(pb[r].y);
            Ws[jr][lk + 2] = to_tf32(pb[r].z); Ws[jr][lk + 3] = to_tf32(pb[r].w);
        }
        __syncthreads();
        if (it < 15) {
            Ag += 32;
            pa = *(const float4*)Ag;
#pragma unroll
            for (int r = 0; r < 3; r++) { Bg[r] += 32; pb[r] = *(const float4*)Bg[r]; }
        }
#pragma unroll
        for (int kk = 0; kk < 32; kk += 8) {
            uint32_t a0 = fbits(As[m0 + g][kk + t]);
            uint32_t a1 = fbits(As[m0 + g + 8][kk + t]);
            uint32_t a2 = fbits(As[m0 + g][kk + t + 4]);
            uint32_t a3 = fbits(As[m0 + g + 8][kk + t + 4]);
#pragma unroll
            for (int f = 0; f < 3; f++) {
                uint32_t b0 = fbits(Ws[n0 + f * 8 + g][kk + t]);
                uint32_t b1 = fbits(Ws[n0 + f * 8 + g][kk + t + 4]);
                mma8(c[f], a0, a1, a2, a3, b0, b1);
            }
        }
        __syncthreads();
    }
#pragma unroll
    for (int f = 0; f < 3; f++) {
        int col0 = n0 + f * 8 + 2 * t;
        *(float2*)&Cs[m0 + g][col0]     = make_float2(c[f][0], c[f][1]);
        *(float2*)&Cs[m0 + g + 8][col0] = make_float2(c[f][2], c[f][3]);
    }
    __syncthreads();
    // pointwise: c = sig(i)*tanh(g); hd = sig(o)*tanh(c)
    int row = tid >> 3;
    int icb = (tid & 7) * 4;
    int brow = bm * 32 + row;
    const float* B1 = bid + sd * GD;
    const float* B2 = bhd + sd * GD;
    float4 ov;
#pragma unroll
    for (int q = 0; q < 4; q++) {
        int ic = icb + q;
        int gcol = bi * 32 + ic;
        float gi = Cs[row][0 * 32 + ic] + B1[0 * IDIM + gcol] + B2[0 * IDIM + gcol];
        float gg = Cs[row][1 * 32 + ic] + B1[2 * IDIM + gcol] + B2[2 * IDIM + gcol];
        float go = Cs[row][2 * 32 + ic] + B1[3 * IDIM + gcol] + B2[3 * IDIM + gcol];
        float cc = sigf(gi) * tanhf(gg);
        (&ov.x)[q] = sigf(go) * tanhf(cc);
    }
    *(float4*)&g_hd[((size_t)sd * BDIM + brow) * IDIM + bi * 32 + icb] = ov;
}

// ---------------- cumsum(4) + tanh + reverse + transpose to (B,I,S) -----------
__global__ void k_final(float* __restrict__ out) {
    int idx = blockIdx.x * 256 + threadIdx.x;  // B*I*(S/4)
    int i = idx & 255;
    int q = (idx >> 8) & 15;
    int b = idx >> 12;
    int base = (4 * q * BDIM + b) * IDIM + i;
    float a0 = g_hd[base];
    float a1 = g_hd[base + 1 * BDIM * IDIM];
    float a2 = g_hd[base + 2 * BDIM * IDIM];
    float a3 = g_hd[base + 3 * BDIM * IDIM];
    float r0 = a0, r1 = r0 + a1, r2 = r1 + a2, r3 = r2 + a3;
    float4 v = make_float4(tanhf(r3), tanhf(r2), tanhf(r1), tanhf(r0));
    *(float4*)(out + (size_t)(b * IDIM + i) * SDIM + (60 - 4 * q)) = v;
}

// ---------------- launch ------------------------------------------------------
extern "C" void kernel_launch(void* const* d_in, const int* in_sizes, int n_in,
                              void* d_out, int out_size) {
    const float* x       = (const float*)d_in[0];
    const float* Wih_enc = (const float*)d_in[1];
    const float* Whh_enc = (const float*)d_in[2];
    const float* bih_enc = (const float*)d_in[3];
    const float* bhh_enc = (const float*)d_in[4];
    const float* Wih_dec = (const float*)d_in[5];
    // d_in[6] = Whh_dec: unused by the reference computation
    const float* bih_dec = (const float*)d_in[7];
    const float* bhh_dec = (const float*)d_in[8];
    float* out = (float*)d_out;

    k_transpose_x<<<2048, 256>>>(x);
    k_zero_h<<<512, 256>>>();
    k_gx<<<dim3(128, 64), 256>>>(Wih_enc, bih_enc, bhh_enc);
    for (int s = 0; s < SDIM; s++) {
        k_enc_step<<<128, 256>>>(Whh_enc, s);
    }
    k_chain<<<512, 256>>>();
    k_dec<<<dim3(64, 64), 256>>>(Wih_dec, bih_dec, bhh_dec);
    k_final<<<4096, 256>>>(out);
}

// round 3
// speedup vs baseline: 1.4221x; 1.0547x over previous
#include <cuda_runtime.h>
#include <math.h>
#include <stdint.h>

#define BDIM 256
#define IDIM 256
#define HDIM 512
#define SDIM 64
#define GE 2048   // 4*H
#define GD 1024   // 4*I

// ---------------- scratch (device globals: allocation-free contract) ----------
__device__ float g_xT[SDIM * BDIM * IDIM];            // x transposed (S,B,I)
__device__ float g_Gx[(size_t)SDIM * BDIM * GE];      // x@Wih^T + biases, all steps
__device__ float g_hA[BDIM * HDIM];                   // hidden state ping
__device__ float g_hB[BDIM * HDIM];                   // hidden state pong
__device__ float g_enc[SDIM * BDIM * HDIM];           // elu(enc) (then residual-chained)
__device__ float g_hd[SDIM * BDIM * IDIM];            // decoder hd

__device__ __forceinline__ float sigf(float x) { return 1.0f / (1.0f + expf(-x)); }

__device__ __forceinline__ float to_tf32(float x) {
    uint32_t u;
    asm("cvt.rna.tf32.f32 %0, %1;" : "=r"(u) : "f"(x));
    return __uint_as_float(u);
}
__device__ __forceinline__ float4 cvt4(float4 v) {
    return make_float4(to_tf32(v.x), to_tf32(v.y), to_tf32(v.z), to_tf32(v.w));
}

__device__ __forceinline__ void mma8(float c[4], uint32_t a0, uint32_t a1,
                                     uint32_t a2, uint32_t a3,
                                     uint32_t b0, uint32_t b1) {
    asm volatile(
        "mma.sync.aligned.m16n8k8.row.col.f32.tf32.tf32.f32 "
        "{%0,%1,%2,%3}, {%4,%5,%6,%7}, {%8,%9}, {%0,%1,%2,%3};\n"
        : "+f"(c[0]), "+f"(c[1]), "+f"(c[2]), "+f"(c[3])
        : "r"(a0), "r"(a1), "r"(a2), "r"(a3), "r"(b0), "r"(b1));
}
__device__ __forceinline__ uint32_t fbits(float x) { return __float_as_uint(x); }

// ---------------- x (B,I,S) -> xT (S,B,I) ------------------------------------
__global__ __launch_bounds__(256) void k_transpose_x(const float* __restrict__ x) {
    __shared__ float tile[32][65];
    int b  = blockIdx.x >> 3;
    int i0 = (blockIdx.x & 7) * 32;
    int tid = threadIdx.x;
    int s = tid & 63, it = tid >> 6;
#pragma unroll
    for (int j = 0; j < 8; j++) {
        int i = it * 8 + j;
        tile[i][s] = x[(b * IDIM + i0 + i) * SDIM + s];
    }
    __syncthreads();
    int i2 = tid & 31, sq = tid >> 5;
#pragma unroll
    for (int j = 0; j < 8; j++) {
        int ss = sq * 8 + j;
        g_xT[(ss * BDIM + b) * IDIM + i0 + i2] = tile[i2][ss];
    }
}

__global__ void k_zero_h() {
    int i = blockIdx.x * 256 + threadIdx.x;
    g_hA[i] = 0.0f;
}

// ============ shared pipeline macros ==========================================
// smem (floats): A stages at 0 / 1152 (32x36 each)
//                B stages at 2304 / 2304+BSTG (NROWSx36 each)
// Cs aliases B stage 0 (only used after the k-loop's final barrier).

// ---------------- Gx[s] = xT[s] @ Wih_enc[s]^T + bih + bhh --------------------
// grid (128, 64): bm=8 x bn=16 (128 n-cols). K=256 -> 8 stages of 32.
__global__ __launch_bounds__(256) void k_gx(const float* __restrict__ Wih,
                                            const float* __restrict__ bih,
                                            const float* __restrict__ bhh) {
    __shared__ float sm[11520];
#define AS_(p, r, k) sm[(p) * 1152 + (r) * 36 + (k)]
#define WS_(p, n, k) sm[2304 + (p) * 4608 + (n) * 36 + (k)]
    int tid = threadIdx.x;
    int s = blockIdx.y;
    int bm = blockIdx.x & 7;
    int bn = blockIdx.x >> 3;

    int ar = tid >> 3, akq = tid & 7;           // A loader: row, k-quad
    int bnr = tid >> 1, bkh = (tid & 1) * 16;   // B loader: row, k-half
    const float* Agp = g_xT + (size_t)(s * BDIM + bm * 32 + ar) * IDIM + akq * 4;
    const float* Bgp = Wih + ((size_t)s * GE + bn * 128 + bnr) * IDIM + bkh;

    int warp = tid >> 5, lane = tid & 31;
    int wm = warp >> 2, wn = warp & 3;
    int g = lane >> 2, t = lane & 3;
    int m0 = wm * 16, n0 = wn * 32;

    float c[4][4] = {};
    float4 ra[2];
    float4 rb[2][4];

    ra[0] = *(const float4*)Agp;
    ra[1] = *(const float4*)(Agp + 32);
#pragma unroll
    for (int j = 0; j < 4; j++) {
        rb[0][j] = *(const float4*)(Bgp + j * 4);
        rb[1][j] = *(const float4*)(Bgp + 32 + j * 4);
    }
    *(float4*)&AS_(0, ar, akq * 4) = cvt4(ra[0]);
#pragma unroll
    for (int j = 0; j < 4; j++)
        *(float4*)&WS_(0, bnr, bkh + j * 4) = cvt4(rb[0][j]);
    __syncthreads();

#pragma unroll 2
    for (int st = 0; st < 8; st++) {
        int p = st & 1;
        if (st < 6) {
            ra[p] = *(const float4*)(Agp + (st + 2) * 32);
#pragma unroll
            for (int j = 0; j < 4; j++)
                rb[p][j] = *(const float4*)(Bgp + (st + 2) * 32 + j * 4);
        }
#pragma unroll
        for (int kk = 0; kk < 32; kk += 8) {
            uint32_t a0 = fbits(AS_(p, m0 + g, kk + t));
            uint32_t a1 = fbits(AS_(p, m0 + g + 8, kk + t));
            uint32_t a2 = fbits(AS_(p, m0 + g, kk + t + 4));
            uint32_t a3 = fbits(AS_(p, m0 + g + 8, kk + t + 4));
#pragma unroll
            for (int f = 0; f < 4; f++) {
                uint32_t b0 = fbits(WS_(p, n0 + f * 8 + g, kk + t));
                uint32_t b1 = fbits(WS_(p, n0 + f * 8 + g, kk + t + 4));
                mma8(c[f], a0, a1, a2, a3, b0, b1);
            }
        }
        if (st < 7) {
            int q = p ^ 1;
            *(float4*)&AS_(q, ar, akq * 4) = cvt4(ra[q]);
#pragma unroll
            for (int j = 0; j < 4; j++)
                *(float4*)&WS_(q, bnr, bkh + j * 4) = cvt4(rb[q][j]);
        }
        __syncthreads();
    }
    // epilogue: add biases, store
#pragma unroll
    for (int f = 0; f < 4; f++) {
        int col = bn * 128 + n0 + f * 8 + 2 * t;
        float bi0 = bih[s * GE + col] + bhh[s * GE + col];
        float bi1 = bih[s * GE + col + 1] + bhh[s * GE + col + 1];
        size_t r0 = ((size_t)s * BDIM + bm * 32 + m0 + g) * GE + col;
        size_t r1 = ((size_t)s * BDIM + bm * 32 + m0 + g + 8) * GE + col;
        *(float2*)&g_Gx[r0] = make_float2(c[f][0] + bi0, c[f][1] + bi1);
        *(float2*)&g_Gx[r1] = make_float2(c[f][2] + bi0, c[f][3] + bi1);
    }
#undef AS_
#undef WS_
}

// ---------------- encoder step: h@Whh^T + fused LSTM pointwise ----------------
// grid 128 = bm(8 x 32 rows) x bh(16 x 32 h-cols). N=128 (4 gates x 32 hcols),
// K=512 -> 16 stages of 32.
__global__ __launch_bounds__(256) void k_enc_step(const float* __restrict__ Whh, int s) {
    __shared__ float sm[11520];
#define AS_(p, r, k) sm[(p) * 1152 + (r) * 36 + (k)]
#define WS_(p, n, k) sm[2304 + (p) * 4608 + (n) * 36 + (k)]
#define CS_(r, cc)   sm[2304 + (r) * 132 + (cc)]
    int tid = threadIdx.x;
    int bm = blockIdx.x & 7;
    int bh = blockIdx.x >> 3;

    const float* hin = (s & 1) ? g_hB : g_hA;
    float* hout      = (s & 1) ? g_hA : g_hB;
    const float* W0 = Whh + (size_t)s * GE * HDIM;

    int ar = tid >> 3, akq = tid & 7;
    int bnr = tid >> 1, bkh = (tid & 1) * 16;
    int bgate = bnr >> 5, bhc = bnr & 31;
    const float* Agp = hin + (size_t)(bm * 32 + ar) * HDIM + akq * 4;
    const float* Bgp = W0 + (size_t)(bgate * HDIM + bh * 32 + bhc) * HDIM + bkh;

    int warp = tid >> 5, lane = tid & 31;
    int wm = warp >> 2, wn = warp & 3;
    int g = lane >> 2, t = lane & 3;
    int m0 = wm * 16, n0 = wn * 32;

    float c[4][4] = {};
    float4 ra[2];
    float4 rb[2][4];

    ra[0] = *(const float4*)Agp;
    ra[1] = *(const float4*)(Agp + 32);
#pragma unroll
    for (int j = 0; j < 4; j++) {
        rb[0][j] = *(const float4*)(Bgp + j * 4);
        rb[1][j] = *(const float4*)(Bgp + 32 + j * 4);
    }
    *(float4*)&AS_(0, ar, akq * 4) = cvt4(ra[0]);
#pragma unroll
    for (int j = 0; j < 4; j++)
        *(float4*)&WS_(0, bnr, bkh + j * 4) = cvt4(rb[0][j]);
    __syncthreads();

#pragma unroll 2
    for (int st = 0; st < 16; st++) {
        int p = st & 1;
        if (st < 14) {
            ra[p] = *(const float4*)(Agp + (st + 2) * 32);
#pragma unroll
            for (int j = 0; j < 4; j++)
                rb[p][j] = *(const float4*)(Bgp + (st + 2) * 32 + j * 4);
        }
#pragma unroll
        for (int kk = 0; kk < 32; kk += 8) {
            uint32_t a0 = fbits(AS_(p, m0 + g, kk + t));
            uint32_t a1 = fbits(AS_(p, m0 + g + 8, kk + t));
            uint32_t a2 = fbits(AS_(p, m0 + g, kk + t + 4));
            uint32_t a3 = fbits(AS_(p, m0 + g + 8, kk + t + 4));
#pragma unroll
            for (int f = 0; f < 4; f++) {
                uint32_t b0 = fbits(WS_(p, n0 + f * 8 + g, kk + t));
                uint32_t b1 = fbits(WS_(p, n0 + f * 8 + g, kk + t + 4));
                mma8(c[f], a0, a1, a2, a3, b0, b1);
            }
        }
        if (st < 15) {
            int q = p ^ 1;
            *(float4*)&AS_(q, ar, akq * 4) = cvt4(ra[q]);
#pragma unroll
            for (int j = 0; j < 4; j++)
                *(float4*)&WS_(q, bnr, bkh + j * 4) = cvt4(rb[q][j]);
        }
        __syncthreads();
    }
    // accumulators -> Cs (aliases B stage 0; safe after the final barrier above)
#pragma unroll
    for (int f = 0; f < 4; f++) {
        int col0 = n0 + f * 8 + 2 * t;
        *(float2*)&CS_(m0 + g, col0)     = make_float2(c[f][0], c[f][1]);
        *(float2*)&CS_(m0 + g + 8, col0) = make_float2(c[f][2], c[f][3]);
    }
    __syncthreads();
    // fused LSTM pointwise + elu (vectorized, 4 elems/thread)
    int row = tid >> 3;
    int hc4 = (tid & 7) * 4;
    int brow = bm * 32 + row;
    const float* Gxp = g_Gx + ((size_t)s * BDIM + brow) * GE + bh * 32;
    float4 gi = *(const float4*)&CS_(row, 0 * 32 + hc4);
    float4 gf = *(const float4*)&CS_(row, 1 * 32 + hc4);
    float4 gg = *(const float4*)&CS_(row, 2 * 32 + hc4);
    float4 go = *(const float4*)&CS_(row, 3 * 32 + hc4);
    float4 xi = *(const float4*)(Gxp + 0 * HDIM + hc4);
    float4 xf = *(const float4*)(Gxp + 1 * HDIM + hc4);
    float4 xg = *(const float4*)(Gxp + 2 * HDIM + hc4);
    float4 xo = *(const float4*)(Gxp + 3 * HDIM + hc4);
    float4 hp = *(const float4*)&hin[(size_t)brow * HDIM + bh * 32 + hc4];
    float4 hv, ev;
#pragma unroll
    for (int q = 0; q < 4; q++) {
        float vi = (&gi.x)[q] + (&xi.x)[q];
        float vf = (&gf.x)[q] + (&xf.x)[q];
        float vg = (&gg.x)[q] + (&xg.x)[q];
        float vo = (&go.x)[q] + (&xo.x)[q];
        float cc = sigf(vf) * (&hp.x)[q] + sigf(vi) * tanhf(vg);
        float hn = sigf(vo) * tanhf(cc);
        (&hv.x)[q] = hn;
        (&ev.x)[q] = hn > 0.0f ? hn : expm1f(hn);
    }
    *(float4*)&hout[(size_t)brow * HDIM + bh * 32 + hc4] = hv;
    *(float4*)&g_enc[(size_t)s * BDIM * HDIM + brow * HDIM + bh * 32 + hc4] = ev;
#undef AS_
#undef WS_
#undef CS_
}

// ---------------- strided residual chain --------------------------------------
__global__ void k_chain() {
    int e = blockIdx.x * 256 + threadIdx.x;
    float prev = g_enc[60 * BDIM * HDIM + e];
#pragma unroll
    for (int k = 0; k < 16; k++) {
        int off = (k * 4) * BDIM * HDIM + e;
        float v = 0.5f * g_enc[off] + 0.5f * prev;
        g_enc[off] = v;
        prev = v;
    }
}

// ---------------- decoder: enc_rev @ Wih_dec^T (i,g,o only) + pointwise -------
// grid (64, 64): bm=8 x bi=8; y = sd. N=96 (3 gates x 32), K=512 -> 16 stages.
__global__ __launch_bounds__(256) void k_dec(const float* __restrict__ Wd,
                                             const float* __restrict__ bid,
                                             const float* __restrict__ bhd) {
    __shared__ float sm[9216];
#define AS_(p, r, k) sm[(p) * 1152 + (r) * 36 + (k)]
#define WS_(p, n, k) sm[2304 + (p) * 3456 + (n) * 36 + (k)]
#define CS_(r, cc)   sm[2304 + (r) * 100 + (cc)]
    int tid = threadIdx.x;
    int sd = blockIdx.y;
    int bm = blockIdx.x & 7;
    int bi = blockIdx.x >> 3;

    int ar = tid >> 3, akq = tid & 7;
    const float* Agp = g_enc + ((size_t)(63 - sd) * BDIM + bm * 32 + ar) * HDIM + akq * 4;
    const int agate[3] = {0, 2, 3};
    // B loader: 3 float4 per thread; idx = tid + 256*jj -> n = idx>>3, kq = idx&7
    const float* Bgp[3];
    int bn_[3], bkq_[3];
#pragma unroll
    for (int jj = 0; jj < 3; jj++) {
        int idx = tid + 256 * jj;
        int n = idx >> 3, kq = idx & 7;
        bn_[jj] = n; bkq_[jj] = kq;
        Bgp[jj] = Wd + ((size_t)sd * GD + agate[n >> 5] * IDIM + bi * 32 + (n & 31)) * HDIM + kq * 4;
    }

    int warp = tid >> 5, lane = tid & 31;
    int wm = warp >> 2, wn = warp & 3;
    int g = lane >> 2, t = lane & 3;
    int m0 = wm * 16, n0 = wn * 24;

    float c[3][4] = {};
    float4 ra[2];
    float4 rb[2][3];

    ra[0] = *(const float4*)Agp;
    ra[1] = *(const float4*)(Agp + 32);
#pragma unroll
    for (int j = 0; j < 3; j++) {
        rb[0][j] = *(const float4*)Bgp[j];
        rb[1][j] = *(const float4*)(Bgp[j] + 32);
    }
    *(float4*)&AS_(0, ar, akq * 4) = cvt4(ra[0]);
#pragma unroll
    for (int j = 0; j < 3; j++)
        *(float4*)&WS_(0, bn_[j], bkq_[j] * 4) = cvt4(rb[0][j]);
    __syncthreads();

#pragma unroll 2
    for (int st = 0; st < 16; st++) {
        int p = st & 1;
        if (st < 14) {
            ra[p] = *(const float4*)(Agp + (st + 2) * 32);
#pragma unroll
            for (int j = 0; j < 3; j++)
                rb[p][j] = *(const float4*)(Bgp[j] + (st + 2) * 32);
        }
#pragma unroll
        for (int kk = 0; kk < 32; kk += 8) {
            uint32_t a0 = fbits(AS_(p, m0 + g, kk + t));
            uint32_t a1 = fbits(AS_(p, m0 + g + 8, kk + t));
            uint32_t a2 = fbits(AS_(p, m0 + g, kk + t + 4));
            uint32_t a3 = fbits(AS_(p, m0 + g + 8, kk + t + 4));
#pragma unroll
            for (int f = 0; f < 3; f++) {
                uint32_t b0 = fbits(WS_(p, n0 + f * 8 + g, kk + t));
                uint32_t b1 = fbits(WS_(p, n0 + f * 8 + g, kk + t + 4));
                mma8(c[f], a0, a1, a2, a3, b0, b1);
            }
        }
        if (st < 15) {
            int q = p ^ 1;
            *(float4*)&AS_(q, ar, akq * 4) = cvt4(ra[q]);
#pragma unroll
            for (int j = 0; j < 3; j++)
                *(float4*)&WS_(q, bn_[j], bkq_[j] * 4) = cvt4(rb[q][j]);
        }
        __syncthreads();
    }
#pragma unroll
    for (int f = 0; f < 3; f++) {
        int col0 = n0 + f * 8 + 2 * t;
        *(float2*)&CS_(m0 + g, col0)     = make_float2(c[f][0], c[f][1]);
        *(float2*)&CS_(m0 + g + 8, col0) = make_float2(c[f][2], c[f][3]);
    }
    __syncthreads();
    // pointwise: cc = sig(i)*tanh(g); hd = sig(o)*tanh(cc)   (4 elems/thread)
    int row = tid >> 3;
    int ic4 = (tid & 7) * 4;
    int brow = bm * 32 + row;
    int gcol = bi * 32 + ic4;
    const float* B1 = bid + sd * GD;
    const float* B2 = bhd + sd * GD;
    float4 gi = *(const float4*)&CS_(row, 0 * 32 + ic4);
    float4 gg = *(const float4*)&CS_(row, 1 * 32 + ic4);
    float4 go = *(const float4*)&CS_(row, 2 * 32 + ic4);
    float4 bi1 = *(const float4*)&B1[0 * IDIM + gcol];
    float4 bi2 = *(const float4*)&B2[0 * IDIM + gcol];
    float4 bg1 = *(const float4*)&B1[2 * IDIM + gcol];
    float4 bg2 = *(const float4*)&B2[2 * IDIM + gcol];
    float4 bo1 = *(const float4*)&B1[3 * IDIM + gcol];
    float4 bo2 = *(const float4*)&B2[3 * IDIM + gcol];
    float4 ov;
#pragma unroll
    for (int q = 0; q < 4; q++) {
        float vi = (&gi.x)[q] + (&bi1.x)[q] + (&bi2.x)[q];
        float vg = (&gg.x)[q] + (&bg1.x)[q] + (&bg2.x)[q];
        float vo = (&go.x)[q] + (&bo1.x)[q] + (&bo2.x)[q];
        float cc = sigf(vi) * tanhf(vg);
        (&ov.x)[q] = sigf(vo) * tanhf(cc);
    }
    *(float4*)&g_hd[((size_t)sd * BDIM + brow) * IDIM + gcol] = ov;
#undef AS_
#undef WS_
#undef CS_
}

// ---------------- cumsum(4) + tanh + reverse + transpose to (B,I,S) -----------
__global__ void k_final(float* __restrict__ out) {
    int idx = blockIdx.x * 256 + threadIdx.x;  // B*I*(S/4)
    int i = idx & 255;
    int q = (idx >> 8) & 15;
    int b = idx >> 12;
    int base = (4 * q * BDIM + b) * IDIM + i;
    float a0 = g_hd[base];
    float a1 = g_hd[base + 1 * BDIM * IDIM];
    float a2 = g_hd[base + 2 * BDIM * IDIM];
    float a3 = g_hd[base + 3 * BDIM * IDIM];
    float r0 = a0, r1 = r0 + a1, r2 = r1 + a2, r3 = r2 + a3;
    float4 v = make_float4(tanhf(r3), tanhf(r2), tanhf(r1), tanhf(r0));
    *(float4*)(out + (size_t)(b * IDIM + i) * SDIM + (60 - 4 * q)) = v;
}

// ---------------- launch ------------------------------------------------------
extern "C" void kernel_launch(void* const* d_in, const int* in_sizes, int n_in,
                              void* d_out, int out_size) {
    const float* x       = (const float*)d_in[0];
    const float* Wih_enc = (const float*)d_in[1];
    const float* Whh_enc = (const float*)d_in[2];
    const float* bih_enc = (const float*)d_in[3];
    const float* bhh_enc = (const float*)d_in[4];
    const float* Wih_dec = (const float*)d_in[5];
    // d_in[6] = Whh_dec: unused by the reference computation
    const float* bih_dec = (const float*)d_in[7];
    const float* bhh_dec = (const float*)d_in[8];
    float* out = (float*)d_out;

    k_transpose_x<<<2048, 256>>>(x);
    k_zero_h<<<512, 256>>>();
    k_gx<<<dim3(128, 64), 256>>>(Wih_enc, bih_enc, bhh_enc);
    for (int s = 0; s < SDIM; s++) {
        k_enc_step<<<128, 256>>>(Whh_enc, s);
    }
    k_chain<<<512, 256>>>();
    k_dec<<<dim3(64, 64), 256>>>(Wih_dec, bih_dec, bhh_dec);
    k_final<<<4096, 256>>>(out);
}

// round 4
// speedup vs baseline: 1.8348x; 1.2902x over previous
#include <cuda_runtime.h>
#include <math.h>
#include <stdint.h>

#define BDIM 256
#define IDIM 256
#define HDIM 512
#define SDIM 64
#define GE 2048   // 4*H
#define GD 1024   // 4*I

// ---------------- scratch (device globals: allocation-free contract) ----------
__device__ float g_xT[SDIM * BDIM * IDIM];            // x transposed (S,B,I)
__device__ float g_Gx[(size_t)SDIM * BDIM * GE];      // x@Wih^T + biases, all steps
__device__ float g_Wt[(size_t)SDIM * GE * HDIM];      // 256MB tf32-rounded Whh_enc
__device__ float g_hA[BDIM * HDIM];                   // hidden fp32 ping
__device__ float g_hB[BDIM * HDIM];                   // hidden fp32 pong
__device__ float g_hTA[BDIM * HDIM];                  // hidden tf32 ping (mma A)
__device__ float g_hTB[BDIM * HDIM];                  // hidden tf32 pong
__device__ float g_enc[SDIM * BDIM * HDIM];           // elu(enc)
__device__ float g_hd[SDIM * BDIM * IDIM];            // decoder hd

__device__ __forceinline__ float sigf(float x) { return 1.0f / (1.0f + expf(-x)); }

__device__ __forceinline__ float to_tf32(float x) {
    uint32_t u;
    asm("cvt.rna.tf32.f32 %0, %1;" : "=r"(u) : "f"(x));
    return __uint_as_float(u);
}
__device__ __forceinline__ float4 cvt4(float4 v) {
    return make_float4(to_tf32(v.x), to_tf32(v.y), to_tf32(v.z), to_tf32(v.w));
}

__device__ __forceinline__ void mma8(float c[4], uint32_t a0, uint32_t a1,
                                     uint32_t a2, uint32_t a3,
                                     uint32_t b0, uint32_t b1) {
    asm volatile(
        "mma.sync.aligned.m16n8k8.row.col.f32.tf32.tf32.f32 "
        "{%0,%1,%2,%3}, {%4,%5,%6,%7}, {%8,%9}, {%0,%1,%2,%3};\n"
        : "+f"(c[0]), "+f"(c[1]), "+f"(c[2]), "+f"(c[3])
        : "r"(a0), "r"(a1), "r"(a2), "r"(a3), "r"(b0), "r"(b1));
}
__device__ __forceinline__ uint32_t fbits(float x) { return __float_as_uint(x); }

__device__ __forceinline__ void cpa16(uint32_t dst, const void* src) {
    asm volatile("cp.async.cg.shared.global [%0], [%1], 16;\n" :: "r"(dst), "l"(src));
}
__device__ __forceinline__ void cpa_commit() {
    asm volatile("cp.async.commit_group;\n");
}
template <int N>
__device__ __forceinline__ void cpa_wait() {
    asm volatile("cp.async.wait_group %0;\n" :: "n"(N));
}

// ---------------- weight pre-convert to tf32 ----------------------------------
__global__ __launch_bounds__(256) void k_cvt_w(const float* __restrict__ W) {
    size_t i = (size_t)blockIdx.x * 256 + threadIdx.x;
    size_t stride = (size_t)gridDim.x * 256;
#pragma unroll
    for (int j = 0; j < 8; j++, i += stride) {
        float4 v = ((const float4*)W)[i];
        ((float4*)g_Wt)[i] = cvt4(v);
    }
}

// ---------------- x (B,I,S) -> xT (S,B,I) ------------------------------------
__global__ __launch_bounds__(256) void k_transpose_x(const float* __restrict__ x) {
    __shared__ float tile[32][65];
    int b  = blockIdx.x >> 3;
    int i0 = (blockIdx.x & 7) * 32;
    int tid = threadIdx.x;
    int s = tid & 63, it = tid >> 6;
#pragma unroll
    for (int j = 0; j < 8; j++) {
        int i = it * 8 + j;
        tile[i][s] = x[(b * IDIM + i0 + i) * SDIM + s];
    }
    __syncthreads();
    int i2 = tid & 31, sq = tid >> 5;
#pragma unroll
    for (int j = 0; j < 8; j++) {
        int ss = sq * 8 + j;
        g_xT[(ss * BDIM + b) * IDIM + i0 + i2] = tile[i2][ss];
    }
}

__global__ void k_zero_h() {
    int i = blockIdx.x * 256 + threadIdx.x;
    g_hA[i] = 0.0f;
    g_hTA[i] = 0.0f;
}

// ---------------- Gx[s] = xT[s] @ Wih_enc[s]^T + bih + bhh --------------------
// grid (128, 64): bm=8 x bn=16 (128 n-cols). K=256 -> 8 stages of 32.
__global__ __launch_bounds__(256) void k_gx(const float* __restrict__ Wih,
                                            const float* __restrict__ bih,
                                            const float* __restrict__ bhh) {
    __shared__ float sm[11520];
#define AS_(p, r, k) sm[(p) * 1152 + (r) * 36 + (k)]
#define WS_(p, n, k) sm[2304 + (p) * 4608 + (n) * 36 + (k)]
    int tid = threadIdx.x;
    int s = blockIdx.y;
    int bm = blockIdx.x & 7;
    int bn = blockIdx.x >> 3;

    int ar = tid >> 3, akq = tid & 7;
    int bnr = tid >> 1, bkh = (tid & 1) * 16;
    const float* Agp = g_xT + (size_t)(s * BDIM + bm * 32 + ar) * IDIM + akq * 4;
    const float* Bgp = Wih + ((size_t)s * GE + bn * 128 + bnr) * IDIM + bkh;

    int warp = tid >> 5, lane = tid & 31;
    int wm = warp >> 2, wn = warp & 3;
    int g = lane >> 2, t = lane & 3;
    int m0 = wm * 16, n0 = wn * 32;

    float c[4][4] = {};
    float4 ra[2];
    float4 rb[2][4];

    ra[0] = *(const float4*)Agp;
    ra[1] = *(const float4*)(Agp + 32);
#pragma unroll
    for (int j = 0; j < 4; j++) {
        rb[0][j] = *(const float4*)(Bgp + j * 4);
        rb[1][j] = *(const float4*)(Bgp + 32 + j * 4);
    }
    *(float4*)&AS_(0, ar, akq * 4) = cvt4(ra[0]);
#pragma unroll
    for (int j = 0; j < 4; j++)
        *(float4*)&WS_(0, bnr, bkh + j * 4) = cvt4(rb[0][j]);
    __syncthreads();

#pragma unroll 2
    for (int st = 0; st < 8; st++) {
        int p = st & 1;
        if (st < 6) {
            ra[p] = *(const float4*)(Agp + (st + 2) * 32);
#pragma unroll
            for (int j = 0; j < 4; j++)
                rb[p][j] = *(const float4*)(Bgp + (st + 2) * 32 + j * 4);
        }
#pragma unroll
        for (int kk = 0; kk < 32; kk += 8) {
            uint32_t a0 = fbits(AS_(p, m0 + g, kk + t));
            uint32_t a1 = fbits(AS_(p, m0 + g + 8, kk + t));
            uint32_t a2 = fbits(AS_(p, m0 + g, kk + t + 4));
            uint32_t a3 = fbits(AS_(p, m0 + g + 8, kk + t + 4));
#pragma unroll
            for (int f = 0; f < 4; f++) {
                uint32_t b0 = fbits(WS_(p, n0 + f * 8 + g, kk + t));
                uint32_t b1 = fbits(WS_(p, n0 + f * 8 + g, kk + t + 4));
                mma8(c[f], a0, a1, a2, a3, b0, b1);
            }
        }
        if (st < 7) {
            int q = p ^ 1;
            *(float4*)&AS_(q, ar, akq * 4) = cvt4(ra[q]);
#pragma unroll
            for (int j = 0; j < 4; j++)
                *(float4*)&WS_(q, bnr, bkh + j * 4) = cvt4(rb[q][j]);
        }
        __syncthreads();
    }
#pragma unroll
    for (int f = 0; f < 4; f++) {
        int col = bn * 128 + n0 + f * 8 + 2 * t;
        float bi0 = bih[s * GE + col] + bhh[s * GE + col];
        float bi1 = bih[s * GE + col + 1] + bhh[s * GE + col + 1];
        size_t r0 = ((size_t)s * BDIM + bm * 32 + m0 + g) * GE + col;
        size_t r1 = ((size_t)s * BDIM + bm * 32 + m0 + g + 8) * GE + col;
        *(float2*)&g_Gx[r0] = make_float2(c[f][0] + bi0, c[f][1] + bi1);
        *(float2*)&g_Gx[r1] = make_float2(c[f][2] + bi0, c[f][3] + bi1);
    }
#undef AS_
#undef WS_
}

// ---------------- encoder step v3: cp.async 3-stage, 256 CTAs -----------------
// grid 256 = bm(8 x 32 rows) x bh(32 x 16 h-cols). CTA: M=32, N=64 (4g x 16hc),
// K=512 -> 16 stages of 32. Stage: A 32x36 + B 64x36 floats.
__global__ __launch_bounds__(256) void k_enc_step(int s) {
    __shared__ float sm[3 * 3456];
#define ESTG 3456
#define EAS_(p, r, k) sm[(p) * ESTG + (r) * 36 + (k)]
#define EWS_(p, n, k) sm[(p) * ESTG + 1152 + (n) * 36 + (k)]
#define ECS_(r, cc)   sm[(r) * 68 + (cc)]
    int tid = threadIdx.x;
    int bm = blockIdx.x & 7;
    int bh = blockIdx.x >> 3;

    const float* hTin = (s & 1) ? g_hTB : g_hTA;
    const float* hin  = (s & 1) ? g_hB  : g_hA;
    float* hTout      = (s & 1) ? g_hTA : g_hTB;
    float* hout       = (s & 1) ? g_hA  : g_hB;

    // A loader: 1 quad/thread. row = tid>>3 (0..31), kq = tid&7
    int arow = tid >> 3, akq = tid & 7;
    const float* Ag = hTin + (size_t)(bm * 32 + arow) * HDIM + akq * 4;
    // B loader: 2 quads/thread. row = tid>>2 (0..63), kq0 = (tid&3)*2
    int brow = tid >> 2, bkq = (tid & 3) * 2;
    int bgate = brow >> 4, bhc = brow & 15;
    const float* Bg = g_Wt + (size_t)s * GE * HDIM +
                      (size_t)((bgate << 9) + bh * 16 + bhc) * HDIM + bkq * 4;

    uint32_t sbase = (uint32_t)__cvta_generic_to_shared(sm);
    uint32_t aoff = (uint32_t)(arow * 36 + akq * 4) * 4;
    uint32_t boff = (uint32_t)(1152 + brow * 36 + bkq * 4) * 4;

    int warp = tid >> 5, lane = tid & 31;
    int g = lane >> 2, t = lane & 3;
    int m0 = (warp >> 2) * 16, n0 = (warp & 3) * 16;

    float c[2][4] = {};

    // prologue: stages 0,1
#pragma unroll
    for (int st = 0; st < 2; st++) {
        uint32_t so = sbase + st * (ESTG * 4);
        cpa16(so + aoff, Ag + st * 32);
        cpa16(so + boff, Bg + st * 32);
        cpa16(so + boff + 16, Bg + st * 32 + 4);
        cpa_commit();
    }

    for (int st = 0; st < 16; st++) {
        if (st < 15) cpa_wait<1>(); else cpa_wait<0>();
        __syncthreads();
        if (st + 2 < 16) {
            int q = (st + 2) % 3;
            uint32_t so = sbase + q * (ESTG * 4);
            cpa16(so + aoff, Ag + (st + 2) * 32);
            cpa16(so + boff, Bg + (st + 2) * 32);
            cpa16(so + boff + 16, Bg + (st + 2) * 32 + 4);
            cpa_commit();
        }
        int p = st % 3;
#pragma unroll
        for (int kk = 0; kk < 32; kk += 8) {
            uint32_t a0 = fbits(EAS_(p, m0 + g, kk + t));
            uint32_t a1 = fbits(EAS_(p, m0 + g + 8, kk + t));
            uint32_t a2 = fbits(EAS_(p, m0 + g, kk + t + 4));
            uint32_t a3 = fbits(EAS_(p, m0 + g + 8, kk + t + 4));
#pragma unroll
            for (int f = 0; f < 2; f++) {
                uint32_t b0 = fbits(EWS_(p, n0 + f * 8 + g, kk + t));
                uint32_t b1 = fbits(EWS_(p, n0 + f * 8 + g, kk + t + 4));
                mma8(c[f], a0, a1, a2, a3, b0, b1);
            }
        }
    }
    __syncthreads();
    // accumulators -> Cs (reuses smem; all copies drained, all reads done)
#pragma unroll
    for (int f = 0; f < 2; f++) {
        int col0 = n0 + f * 8 + 2 * t;
        *(float2*)&ECS_(m0 + g, col0)     = make_float2(c[f][0], c[f][1]);
        *(float2*)&ECS_(m0 + g + 8, col0) = make_float2(c[f][2], c[f][3]);
    }
    __syncthreads();
    // fused LSTM pointwise + elu: 2 elems/thread
    int row = tid >> 3;
    int hc2 = (tid & 7) * 2;
    int brow2 = bm * 32 + row;
    const float* Gxp = g_Gx + ((size_t)s * BDIM + brow2) * GE + bh * 16 + hc2;
    float2 gi = *(const float2*)&ECS_(row, 0 * 16 + hc2);
    float2 gf = *(const float2*)&ECS_(row, 1 * 16 + hc2);
    float2 gg = *(const float2*)&ECS_(row, 2 * 16 + hc2);
    float2 go = *(const float2*)&ECS_(row, 3 * 16 + hc2);
    float2 xi = *(const float2*)(Gxp + 0 * HDIM);
    float2 xf = *(const float2*)(Gxp + 1 * HDIM);
    float2 xg = *(const float2*)(Gxp + 2 * HDIM);
    float2 xo = *(const float2*)(Gxp + 3 * HDIM);
    float2 hp = *(const float2*)&hin[(size_t)brow2 * HDIM + bh * 16 + hc2];
    float2 hv, tv, ev;
#pragma unroll
    for (int q = 0; q < 2; q++) {
        float vi = (&gi.x)[q] + (&xi.x)[q];
        float vf = (&gf.x)[q] + (&xf.x)[q];
        float vg = (&gg.x)[q] + (&xg.x)[q];
        float vo = (&go.x)[q] + (&xo.x)[q];
        float cc = sigf(vf) * (&hp.x)[q] + sigf(vi) * tanhf(vg);
        float hn = sigf(vo) * tanhf(cc);
        (&hv.x)[q] = hn;
        (&tv.x)[q] = to_tf32(hn);
        (&ev.x)[q] = hn > 0.0f ? hn : expm1f(hn);
    }
    size_t ho = (size_t)brow2 * HDIM + bh * 16 + hc2;
    *(float2*)&hout[ho] = hv;
    *(float2*)&hTout[ho] = tv;
    *(float2*)&g_enc[(size_t)s * BDIM * HDIM + ho] = ev;
#undef EAS_
#undef EWS_
#undef ECS_
#undef ESTG
}

// ---------------- strided residual chain --------------------------------------
__global__ void k_chain() {
    int e = blockIdx.x * 256 + threadIdx.x;
    float prev = g_enc[60 * BDIM * HDIM + e];
#pragma unroll
    for (int k = 0; k < 16; k++) {
        int off = (k * 4) * BDIM * HDIM + e;
        float v = 0.5f * g_enc[off] + 0.5f * prev;
        g_enc[off] = v;
        prev = v;
    }
}

// ---------------- decoder: enc_rev @ Wih_dec^T (i,g,o only) + pointwise -------
// grid (64, 64): bm=8 x bi=8; y = sd. N=96 (3 gates x 32), K=512 -> 16 stages.
__global__ __launch_bounds__(256) void k_dec(const float* __restrict__ Wd,
                                             const float* __restrict__ bid,
                                             const float* __restrict__ bhd) {
    __shared__ float sm[9216];
#define AS_(p, r, k) sm[(p) * 1152 + (r) * 36 + (k)]
#define WS_(p, n, k) sm[2304 + (p) * 3456 + (n) * 36 + (k)]
#define CS_(r, cc)   sm[2304 + (r) * 100 + (cc)]
    int tid = threadIdx.x;
    int sd = blockIdx.y;
    int bm = blockIdx.x & 7;
    int bi = blockIdx.x >> 3;

    int ar = tid >> 3, akq = tid & 7;
    const float* Agp = g_enc + ((size_t)(63 - sd) * BDIM + bm * 32 + ar) * HDIM + akq * 4;
    const int agate[3] = {0, 2, 3};
    const float* Bgp[3];
    int bn_[3], bkq_[3];
#pragma unroll
    for (int jj = 0; jj < 3; jj++) {
        int idx = tid + 256 * jj;
        int n = idx >> 3, kq = idx & 7;
        bn_[jj] = n; bkq_[jj] = kq;
        Bgp[jj] = Wd + ((size_t)sd * GD + agate[n >> 5] * IDIM + bi * 32 + (n & 31)) * HDIM + kq * 4;
    }

    int warp = tid >> 5, lane = tid & 31;
    int wm = warp >> 2, wn = warp & 3;
    int g = lane >> 2, t = lane & 3;
    int m0 = wm * 16, n0 = wn * 24;

    float c[3][4] = {};
    float4 ra[2];
    float4 rb[2][3];

    ra[0] = *(const float4*)Agp;
    ra[1] = *(const float4*)(Agp + 32);
#pragma unroll
    for (int j = 0; j < 3; j++) {
        rb[0][j] = *(const float4*)Bgp[j];
        rb[1][j] = *(const float4*)(Bgp[j] + 32);
    }
    *(float4*)&AS_(0, ar, akq * 4) = cvt4(ra[0]);
#pragma unroll
    for (int j = 0; j < 3; j++)
        *(float4*)&WS_(0, bn_[j], bkq_[j] * 4) = cvt4(rb[0][j]);
    __syncthreads();

#pragma unroll 2
    for (int st = 0; st < 16; st++) {
        int p = st & 1;
        if (st < 14) {
            ra[p] = *(const float4*)(Agp + (st + 2) * 32);
#pragma unroll
            for (int j = 0; j < 3; j++)
                rb[p][j] = *(const float4*)(Bgp[j] + (st + 2) * 32);
        }
#pragma unroll
        for (int kk = 0; kk < 32; kk += 8) {
            uint32_t a0 = fbits(AS_(p, m0 + g, kk + t));
            uint32_t a1 = fbits(AS_(p, m0 + g + 8, kk + t));
            uint32_t a2 = fbits(AS_(p, m0 + g, kk + t + 4));
            uint32_t a3 = fbits(AS_(p, m0 + g + 8, kk + t + 4));
#pragma unroll
            for (int f = 0; f < 3; f++) {
                uint32_t b0 = fbits(WS_(p, n0 + f * 8 + g, kk + t));
                uint32_t b1 = fbits(WS_(p, n0 + f * 8 + g, kk + t + 4));
                mma8(c[f], a0, a1, a2, a3, b0, b1);
            }
        }
        if (st < 15) {
            int q = p ^ 1;
            *(float4*)&AS_(q, ar, akq * 4) = cvt4(ra[q]);
#pragma unroll
            for (int j = 0; j < 3; j++)
                *(float4*)&WS_(q, bn_[j], bkq_[j] * 4) = cvt4(rb[q][j]);
        }
        __syncthreads();
    }
#pragma unroll
    for (int f = 0; f < 3; f++) {
        int col0 = n0 + f * 8 + 2 * t;
        *(float2*)&CS_(m0 + g, col0)     = make_float2(c[f][0], c[f][1]);
        *(float2*)&CS_(m0 + g + 8, col0) = make_float2(c[f][2], c[f][3]);
    }
    __syncthreads();
    int row = tid >> 3;
    int ic4 = (tid & 7) * 4;
    int brow = bm * 32 + row;
    int gcol = bi * 32 + ic4;
    const float* B1 = bid + sd * GD;
    const float* B2 = bhd + sd * GD;
    float4 gi = *(const float4*)&CS_(row, 0 * 32 + ic4);
    float4 gg = *(const float4*)&CS_(row, 1 * 32 + ic4);
    float4 go = *(const float4*)&CS_(row, 2 * 32 + ic4);
    float4 bi1 = *(const float4*)&B1[0 * IDIM + gcol];
    float4 bi2 = *(const float4*)&B2[0 * IDIM + gcol];
    float4 bg1 = *(const float4*)&B1[2 * IDIM + gcol];
    float4 bg2 = *(const float4*)&B2[2 * IDIM + gcol];
    float4 bo1 = *(const float4*)&B1[3 * IDIM + gcol];
    float4 bo2 = *(const float4*)&B2[3 * IDIM + gcol];
    float4 ov;
#pragma unroll
    for (int q = 0; q < 4; q++) {
        float vi = (&gi.x)[q] + (&bi1.x)[q] + (&bi2.x)[q];
        float vg = (&gg.x)[q] + (&bg1.x)[q] + (&bg2.x)[q];
        float vo = (&go.x)[q] + (&bo1.x)[q] + (&bo2.x)[q];
        float cc = sigf(vi) * tanhf(vg);
        (&ov.x)[q] = sigf(vo) * tanhf(cc);
    }
    *(float4*)&g_hd[((size_t)sd * BDIM + brow) * IDIM + gcol] = ov;
#undef AS_
#undef WS_
#undef CS_
}

// ---------------- cumsum(4) + tanh + reverse + transpose to (B,I,S) -----------
__global__ void k_final(float* __restrict__ out) {
    int idx = blockIdx.x * 256 + threadIdx.x;  // B*I*(S/4)
    int i = idx & 255;
    int q = (idx >> 8) & 15;
    int b = idx >> 12;
    int base = (4 * q * BDIM + b) * IDIM + i;
    float a0 = g_hd[base];
    float a1 = g_hd[base + 1 * BDIM * IDIM];
    float a2 = g_hd[base + 2 * BDIM * IDIM];
    float a3 = g_hd[base + 3 * BDIM * IDIM];
    float r0 = a0, r1 = r0 + a1, r2 = r1 + a2, r3 = r2 + a3;
    float4 v = make_float4(tanhf(r3), tanhf(r2), tanhf(r1), tanhf(r0));
    *(float4*)(out + (size_t)(b * IDIM + i) * SDIM + (60 - 4 * q)) = v;
}

// ---------------- launch ------------------------------------------------------
extern "C" void kernel_launch(void* const* d_in, const int* in_sizes, int n_in,
                              void* d_out, int out_size) {
    const float* x       = (const float*)d_in[0];
    const float* Wih_enc = (const float*)d_in[1];
    const float* Whh_enc = (const float*)d_in[2];
    const float* bih_enc = (const float*)d_in[3];
    const float* bhh_enc = (const float*)d_in[4];
    const float* Wih_dec = (const float*)d_in[5];
    // d_in[6] = Whh_dec: unused by the reference computation
    const float* bih_dec = (const float*)d_in[7];
    const float* bhh_dec = (const float*)d_in[8];
    float* out = (float*)d_out;

    k_cvt_w<<<8192, 256>>>(Whh_enc);
    k_transpose_x<<<2048, 256>>>(x);
    k_zero_h<<<512, 256>>>();
    k_gx<<<dim3(128, 64), 256>>>(Wih_enc, bih_enc, bhh_enc);
    for (int s = 0; s < SDIM; s++) {
        k_enc_step<<<256, 256>>>(s);
    }
    k_chain<<<512, 256>>>();
    k_dec<<<dim3(64, 64), 256>>>(Wih_dec, bih_dec, bhh_dec);
    k_final<<<4096, 256>>>(out);
}